// round 8
// baseline (speedup 1.0000x reference)
#include <cuda_runtime.h>
#include <cuda_fp16.h>
#include <cstdint>
#include <cstdio>

#define BATCH 32
#define TSEQ  48
#define EDIM  128
#define TDIM  48
#define DIN   176
#define HDIM  256
#define GDIM  768
#define OUTL  40000
#define OUTC  40048
#define MROWS 1536
#define NTILES 313            /* ceil(40048/128) */
#define NPAD  (NTILES * 128)  /* 40064 */
#define REC_SMEM ((192 * 260 + 512 + 192 + 384) * 4) /* 204032 B */

// ------------------ device scratch (no allocation allowed) ------------------
__device__ float g_X0[MROWS * DIN];
__device__ float g_XP[MROWS * GDIM];
__device__ float g_Y0[MROWS * HDIM];
__device__ float g_Y1[MROWS * HDIM];
__device__ uint4 g_Apack[(MROWS / 16) * 16 * 32];
__device__ uint2 g_Bpack[(NPAD / 8) * 16 * 32];
__device__ float g_ploc[MROWS * NTILES];
__device__ float g_ptm[MROWS];
__device__ float g_lse[MROWS * 2];

// ------------------ helpers ------------------
__device__ __forceinline__ uint32_t smem_u32(const void* p) {
    uint32_t a;
    asm("{ .reg .u64 t; cvta.to.shared.u64 t, %1; cvt.u32.u64 %0, t; }" : "=r"(a) : "l"(p));
    return a;
}
__device__ __forceinline__ uint32_t pk(float a, float b) {
    __half2 h = __floats2half2_rn(a, b);
    return *(uint32_t*)&h;
}

// ------------------ K0: embedding gather + one-hot time ------------------
__global__ void k_embed(const int* __restrict__ loc, const int* __restrict__ tim,
                        const float* __restrict__ emb, float* __restrict__ X0) {
    int idx = blockIdx.x * blockDim.x + threadIdx.x;
    if (idx >= MROWS * DIN) return;
    int m = idx / DIN, c = idx - m * DIN;   // m = b*48 + t, matches [B,T] flat
    float v;
    if (c < EDIM) v = emb[(size_t)loc[m] * EDIM + c];
    else          v = (tim[m] == (c - EDIM)) ? 1.0f : 0.0f;
    X0[idx] = v;
}

// ------------------ K1: fp32 GEMM  C[M,N] = A[M,K] @ W[N,K]^T + bias -------
// 64x64 tiles, BK=16, 256 threads. M,N mult of 64; K mult of 16.
__global__ void __launch_bounds__(256) k_gemm64(const float* __restrict__ A,
                                                const float* __restrict__ W,
                                                const float* __restrict__ bias,
                                                float* __restrict__ C,
                                                int M, int N, int K) {
    __shared__ float As[16][68];
    __shared__ float Bs[16][68];
    int tid = threadIdx.x;
    int bm = blockIdx.y * 64, bn = blockIdx.x * 64;
    int tx = tid & 15, ty = tid >> 4;
    int lr = tid >> 2, lc = (tid & 3) * 4;
    float acc[4][4] = {};
    for (int k0 = 0; k0 < K; k0 += 16) {
        float4 a = *(const float4*)(A + (size_t)(bm + lr) * K + k0 + lc);
        float4 w = *(const float4*)(W + (size_t)(bn + lr) * K + k0 + lc);
        As[lc + 0][lr] = a.x; As[lc + 1][lr] = a.y; As[lc + 2][lr] = a.z; As[lc + 3][lr] = a.w;
        Bs[lc + 0][lr] = w.x; Bs[lc + 1][lr] = w.y; Bs[lc + 2][lr] = w.z; Bs[lc + 3][lr] = w.w;
        __syncthreads();
#pragma unroll
        for (int kk = 0; kk < 16; kk++) {
            float4 av = *(const float4*)&As[kk][ty * 4];
            float4 bv = *(const float4*)&Bs[kk][tx * 4];
            float aa[4] = {av.x, av.y, av.z, av.w};
            float bb[4] = {bv.x, bv.y, bv.z, bv.w};
#pragma unroll
            for (int i = 0; i < 4; i++)
#pragma unroll
                for (int j = 0; j < 4; j++) acc[i][j] += aa[i] * bb[j];
        }
        __syncthreads();
    }
#pragma unroll
    for (int i = 0; i < 4; i++)
#pragma unroll
        for (int j = 0; j < 4; j++) {
            int n = bn + tx * 4 + j;
            C[(size_t)(bm + ty * 4 + i) * N + n] = acc[i][j] + bias[n];
        }
}

// ------------------ K2: GRU recurrence (cluster of 4 CTAs per batch) -------
// CTA (b,part) owns gate rows {g*256 + part*64 + j : g<3, j<64} of w_hh,
// resident in smem [192][260] fp32. Full h double-buffered in smem; the 64
// updated h values are broadcast to all 4 cluster CTAs via DSMEM each step.
__global__ void __launch_bounds__(256, 1) __cluster_dims__(4, 1, 1)
k_rec(const float* __restrict__ xp, const float* __restrict__ w_hh,
      const float* __restrict__ b_hh, const float* __restrict__ traj,
      const int* __restrict__ labels, float* __restrict__ y, int layer) {
    extern __shared__ float sm[];
    float* WT = sm;                    // [192][260]
    float* HB = sm + 192 * 260;        // [2][256]
    float* HP = HB + 512;              // [192]
    float* XB = HP + 192;              // [2][192]
    const int tid = threadIdx.x;
    const int b = blockIdx.x >> 2, part = blockIdx.x & 3;

    for (int s = 0; s < 192; s++) {
        int row = (s >> 6) * 256 + part * 64 + (s & 63);
        WT[s * 260 + tid] = w_hh[row * 256 + tid];
    }
    {   // raw-reshape h0 semantics
        int lb = labels[layer * 16 + (b >> 1)];
        HB[tid] = traj[lb * 512 + (b & 1) * 256 + tid];
    }
    float bh = 0.f;
    if (tid < 192)
        bh = b_hh[(tid >> 6) * 256 + part * 64 + (tid & 63)];
    if (tid >= 192) {   // prefetch xp for t=0
        int s0 = tid - 192;
        int base2 = (b * 48) * 768 + part * 64;
        for (int g = 0; g < 3; g++)
            XB[g * 64 + s0] = xp[base2 + g * 256 + s0];
    }
    asm volatile("barrier.cluster.arrive.aligned;\n\tbarrier.cluster.wait.aligned;" ::: "memory");

    for (int t = 0; t < 48; t++) {
        const float* hc = HB + (t & 1) * 256;
        float* hnx = HB + ((t + 1) & 1) * 256;
        if (tid < 192) {
            const float4* w4 = (const float4*)(WT + tid * 260);
            const float4* h4 = (const float4*)hc;
            float a0 = bh, a1 = 0.f, a2 = 0.f, a3 = 0.f;
#pragma unroll 16
            for (int k = 0; k < 64; k++) {
                float4 w = w4[k], h = h4[k];
                a0 += w.x * h.x; a1 += w.y * h.y; a2 += w.z * h.z; a3 += w.w * h.w;
            }
            HP[tid] = (a0 + a1) + (a2 + a3);
        } else if (t + 1 < 48) {       // prefetch next step's xp
            int s0 = tid - 192;
            int base2 = (b * 48 + t + 1) * 768 + part * 64;
            float* xd = XB + ((t + 1) & 1) * 192;
            for (int g = 0; g < 3; g++)
                xd[g * 64 + s0] = xp[base2 + g * 256 + s0];
        }
        __syncthreads();
        if (tid < 64) {
            const float* xc = XB + (t & 1) * 192;
            float xr = xc[tid], xz = xc[64 + tid], xn = xc[128 + tid];
            float hr = HP[tid], hz = HP[64 + tid], hn = HP[128 + tid];
            float r = 1.f / (1.f + expf(-(xr + hr)));
            float z = 1.f / (1.f + expf(-(xz + hz)));
            float n = tanhf(xn + r * hn);
            int hi = part * 64 + tid;
            float hv = (1.f - z) * n + z * hc[hi];
            y[(size_t)(b * 48 + t) * 256 + hi] = hv;
            uint32_t la = smem_u32(&hnx[hi]);
#pragma unroll
            for (int rk = 0; rk < 4; rk++) {
                asm volatile("{ .reg .b32 ra; mapa.shared::cluster.u32 ra, %0, %1; "
                             "st.shared::cluster.f32 [ra], %2; }"
                             :: "r"(la), "r"(rk), "f"(hv) : "memory");
            }
        }
        asm volatile("barrier.cluster.arrive.aligned;\n\tbarrier.cluster.wait.aligned;" ::: "memory");
    }
}

// ------------------ K3: operand packing for fp16 mma ------------------
// A frag per lane (16B): {A[r][c0],A[r][c0+1]},{A[r+8][c0],..},{A[r][c0+8],..},{A[r+8][c0+8],..}
__global__ void k_packA() {
    int g = blockIdx.x * blockDim.x + threadIdx.x;
    if (g >= (MROWS / 16) * 16 * 32) return;
    int lane = g & 31, kt = (g >> 5) & 15, mt = g >> 9;
    int r = mt * 16 + (lane >> 2);
    int c0 = kt * 16 + (lane & 3) * 2;
    const float* p0 = g_Y1 + (size_t)r * HDIM + c0;
    const float* p1 = p0 + 8 * HDIM;
#define RL(x) fmaxf((x), 0.f)
    g_Apack[g] = make_uint4(pk(RL(p0[0]), RL(p0[1])), pk(RL(p1[0]), RL(p1[1])),
                            pk(RL(p0[8]), RL(p0[9])), pk(RL(p1[8]), RL(p1[9])));
#undef RL
}
// B frag per lane (8B): {W[n][k0],W[n][k0+1]},{W[n][k0+8],W[n][k0+9]}
__global__ void k_packB(const float* __restrict__ fw) {
    int g = blockIdx.x * blockDim.x + threadIdx.x;
    if (g >= (NPAD / 8) * 16 * 32) return;
    int lane = g & 31, kt = (g >> 5) & 15, nt = g >> 9;
    int n = nt * 8 + (lane >> 2);
    int k0 = kt * 16 + (lane & 3) * 2;
    float w00 = 0.f, w01 = 0.f, w08 = 0.f, w09 = 0.f;
    if (n < OUTC) {
        const float* r = fw + (size_t)n * HDIM + k0;
        w00 = r[0]; w01 = r[1]; w08 = r[8]; w09 = r[9];
    }
    g_Bpack[g] = make_uint2(pk(w00, w01), pk(w08, w09));
}

// ------------------ K4: fc GEMM (fp16 mma, fp32 acc) + exp partial sums ----
__global__ void __launch_bounds__(256) k_fc(const float* __restrict__ fc_b,
                                            float* __restrict__ out_loc,
                                            float* __restrict__ out_tm) {
    const int lane = threadIdx.x & 31, w = threadIdx.x >> 5;
    const int wm = (w >> 2) * 64, wn = (w & 3) * 32;
    const int m0 = blockIdx.y * 128, n0 = blockIdx.x * 128;
    const int mtb = (m0 + wm) >> 4, ntb = (n0 + wn) >> 3;
    float acc[4][4][4];
#pragma unroll
    for (int i = 0; i < 4; i++)
#pragma unroll
        for (int j = 0; j < 4; j++) {
            acc[i][j][0] = 0.f; acc[i][j][1] = 0.f; acc[i][j][2] = 0.f; acc[i][j][3] = 0.f;
        }
    for (int kt = 0; kt < 16; kt++) {
        uint4 af[4]; uint2 bf[4];
#pragma unroll
        for (int i = 0; i < 4; i++) af[i] = g_Apack[((size_t)(mtb + i) * 16 + kt) * 32 + lane];
#pragma unroll
        for (int j = 0; j < 4; j++) bf[j] = g_Bpack[((size_t)(ntb + j) * 16 + kt) * 32 + lane];
#pragma unroll
        for (int i = 0; i < 4; i++)
#pragma unroll
            for (int j = 0; j < 4; j++)
                asm volatile("mma.sync.aligned.m16n8k16.row.col.f32.f16.f16.f32 "
                             "{%0,%1,%2,%3},{%4,%5,%6,%7},{%8,%9},{%0,%1,%2,%3};"
                             : "+f"(acc[i][j][0]), "+f"(acc[i][j][1]),
                               "+f"(acc[i][j][2]), "+f"(acc[i][j][3])
                             : "r"(af[i].x), "r"(af[i].y), "r"(af[i].z), "r"(af[i].w),
                               "r"(bf[j].x), "r"(bf[j].y));
    }
    float sl[4][2] = {}, stm[4][2] = {};
#pragma unroll
    for (int i = 0; i < 4; i++) {
#pragma unroll
        for (int j = 0; j < 4; j++) {
            int cb = n0 + wn + j * 8 + (lane & 3) * 2;       // even; pairs never straddle group edges
            float b0 = (cb < OUTC) ? __ldg(&fc_b[cb]) : 0.f;
            float b1 = (cb + 1 < OUTC) ? __ldg(&fc_b[cb + 1]) : 0.f;
#pragma unroll
            for (int h = 0; h < 2; h++) {
                int gm = m0 + wm + i * 16 + (lane >> 2) + h * 8;
                float v0 = acc[i][j][h * 2 + 0] + b0;
                float v1 = acc[i][j][h * 2 + 1] + b1;
                if (cb < OUTL) {
                    *(float2*)&out_loc[(size_t)gm * OUTL + cb] = make_float2(v0, v1);
                    sl[i][h] += __expf(v0) + __expf(v1);
                } else if (cb < OUTC) {
                    *(float2*)&out_tm[(size_t)gm * TDIM + (cb - OUTL)] = make_float2(v0, v1);
                    stm[i][h] += __expf(v0) + __expf(v1);
                }
            }
        }
    }
    __shared__ float sp_loc[128][4];
    __shared__ float sp_tm[128][4];
#pragma unroll
    for (int i = 0; i < 4; i++)
#pragma unroll
        for (int h = 0; h < 2; h++) {
            float v = sl[i][h];
            v += __shfl_xor_sync(0xffffffffu, v, 1);
            v += __shfl_xor_sync(0xffffffffu, v, 2);
            float vt = stm[i][h];
            vt += __shfl_xor_sync(0xffffffffu, vt, 1);
            vt += __shfl_xor_sync(0xffffffffu, vt, 2);
            if ((lane & 3) == 0) {
                int lr = wm + i * 16 + (lane >> 2) + h * 8;
                sp_loc[lr][w & 3] = v;
                sp_tm[lr][w & 3] = vt;
            }
        }
    __syncthreads();
    if (threadIdx.x < 128) {
        int lr = threadIdx.x;
        // fixed-order adds -> deterministic
        float p = ((sp_loc[lr][0] + sp_loc[lr][1]) + sp_loc[lr][2]) + sp_loc[lr][3];
        g_ploc[(size_t)(m0 + lr) * NTILES + blockIdx.x] = p;
        if (blockIdx.x == NTILES - 1)
            g_ptm[m0 + lr] = ((sp_tm[lr][0] + sp_tm[lr][1]) + sp_tm[lr][2]) + sp_tm[lr][3];
    }
}

// ------------------ K5: logsumexp reduce (deterministic order) -------------
__global__ void k_lse() {
    int r = blockIdx.x * blockDim.x + threadIdx.x;
    if (r >= MROWS) return;
    float s = 0.f;
    const float* p = g_ploc + (size_t)r * NTILES;
    for (int i = 0; i < NTILES; i++) s += p[i];
    g_lse[r * 2 + 0] = logf(s);
    g_lse[r * 2 + 1] = logf(g_ptm[r]);
}

// ------------------ K6: in-place normalize ------------------
__global__ void k_norm(float* __restrict__ out) {
    const long long NL4 = (long long)MROWS * OUTL / 4;
    const long long NT4 = (long long)MROWS * TDIM / 4;
    long long idx = (long long)blockIdx.x * blockDim.x + threadIdx.x;
    if (idx >= NL4 + NT4) return;
    float4* o4 = (float4*)out;
    float l;
    if (idx < NL4) {
        int row = (int)((idx * 4) / OUTL);   // 40000 % 4 == 0: all 4 same row
        l = g_lse[row * 2];
    } else {
        long long i = idx - NL4;
        int row = (int)((i * 4) / TDIM);     // 48 % 4 == 0
        l = g_lse[row * 2 + 1];
    }
    float4 v = o4[idx];
    v.x -= l; v.y -= l; v.z -= l; v.w -= l;
    o4[idx] = v;
}

// ------------------ launch ------------------
extern "C" void kernel_launch(void* const* d_in, const int* in_sizes, int n_in,
                              void* d_out, int out_size) {
    (void)in_sizes; (void)n_in; (void)out_size;
    const int*   loc  = (const int*)d_in[0];
    const int*   tim  = (const int*)d_in[1];
    const int*   lab  = (const int*)d_in[2];
    const float* emb  = (const float*)d_in[3];
    const float* traj = (const float*)d_in[4];
    const float* fw   = (const float*)d_in[5];
    const float* fb   = (const float*)d_in[6];
    const float* wih0 = (const float*)d_in[7];
    const float* whh0 = (const float*)d_in[8];
    const float* bih0 = (const float*)d_in[9];
    const float* bhh0 = (const float*)d_in[10];
    const float* wih1 = (const float*)d_in[11];
    const float* whh1 = (const float*)d_in[12];
    const float* bih1 = (const float*)d_in[13];
    const float* bhh1 = (const float*)d_in[14];
    float* out = (float*)d_out;

    cudaFuncSetAttribute((const void*)k_rec,
                         cudaFuncAttributeMaxDynamicSharedMemorySize, REC_SMEM);

    void *pX0, *pXP, *pY0, *pY1;
    cudaGetSymbolAddress(&pX0, g_X0);
    cudaGetSymbolAddress(&pXP, g_XP);
    cudaGetSymbolAddress(&pY0, g_Y0);
    cudaGetSymbolAddress(&pY1, g_Y1);

    k_embed<<<(MROWS * DIN + 255) / 256, 256>>>(loc, tim, emb, (float*)pX0);
    k_packB<<<((NPAD / 8) * 16 * 32 + 255) / 256, 256>>>(fw);

    k_gemm64<<<dim3(GDIM / 64, MROWS / 64), 256>>>((const float*)pX0, wih0, bih0,
                                                   (float*)pXP, MROWS, GDIM, DIN);
    k_rec<<<128, 256, REC_SMEM>>>((const float*)pXP, whh0, bhh0, traj, lab, (float*)pY0, 0);

    k_gemm64<<<dim3(GDIM / 64, MROWS / 64), 256>>>((const float*)pY0, wih1, bih1,
                                                   (float*)pXP, MROWS, GDIM, HDIM);
    k_rec<<<128, 256, REC_SMEM>>>((const float*)pXP, whh1, bhh1, traj, lab, (float*)pY1, 1);

    k_packA<<<((MROWS / 16) * 16 * 32 + 255) / 256, 256>>>();
    k_fc<<<dim3(NTILES, MROWS / 128), 256>>>(fb, out, out + (size_t)MROWS * OUTL);
    k_lse<<<(MROWS + 255) / 256, 256>>>();

    long long tot4 = (long long)MROWS * OUTL / 4 + (long long)MROWS * TDIM / 4;
    k_norm<<<(unsigned)((tot4 + 255) / 256), 256>>>(out);
}